// round 1
// baseline (speedup 1.0000x reference)
#include <cuda_runtime.h>
#include <cuda_bf16.h>
#include <cstdint>

// Problem constants (B=1)
#define NUM_HEADS 16
#define SEQ_LEN   4096
#define HEAD_DIM  128
#define D_MODEL   (NUM_HEADS * HEAD_DIM)

// Tiling
#define BM 128      // Q rows per CTA
#define BN 64       // KV rows per tile
#define THREADS 256 // 8 warps, 16 Q rows each

// SMEM strides (floats), chosen for conflict-free fragment loads
#define SQ_STRIDE 132   // bank = 4*row + dlane  -> distinct
#define SK_STRIDE 132   // bank = 4*n   + dlane  -> distinct
#define SV_STRIDE 136   // bank = 8*klane + nlane -> distinct
#define SP_STRIDE 68    // bank = 4*row + klane  -> distinct

#define SMEM_FLOATS (BM*SQ_STRIDE + BN*SK_STRIDE + BN*SV_STRIDE + BM*SP_STRIDE)
#define SMEM_BYTES  (SMEM_FLOATS * 4)   // 171,008 B

__device__ __forceinline__ unsigned f2tf(float f) {
    unsigned r;
    asm("cvt.rna.tf32.f32 %0, %1;" : "=r"(r) : "f"(f));
    return r;
}
__device__ __forceinline__ float ex2f(float x) {
    float r;
    asm("ex2.approx.ftz.f32 %0, %1;" : "=f"(r) : "f"(x));
    return r;
}
__device__ __forceinline__ void mma_tf32(float c[4],
    unsigned a0, unsigned a1, unsigned a2, unsigned a3,
    unsigned b0, unsigned b1)
{
    asm volatile(
        "mma.sync.aligned.m16n8k8.row.col.f32.tf32.tf32.f32 "
        "{%0,%1,%2,%3}, {%4,%5,%6,%7}, {%8,%9}, {%0,%1,%2,%3};\n"
        : "+f"(c[0]), "+f"(c[1]), "+f"(c[2]), "+f"(c[3])
        : "r"(a0), "r"(a1), "r"(a2), "r"(a3), "r"(b0), "r"(b1));
}

extern __shared__ float smem[];

__global__ __launch_bounds__(THREADS, 1)
void fa_tf32_kernel(const float* __restrict__ Q, const float* __restrict__ K,
                    const float* __restrict__ V, float* __restrict__ Out)
{
    // Heavy causal tiles (high qt) launch first for wave balance
    const int qt   = (int)gridDim.x - 1 - (int)blockIdx.x;
    const int head = blockIdx.y;
    const int q0   = qt * BM;

    float* sQ = smem;
    float* sK = sQ + BM * SQ_STRIDE;
    float* sV = sK + BN * SK_STRIDE;
    float* sP = sV + BN * SV_STRIDE;

    const int tid  = threadIdx.x;
    const int lane = tid & 31;
    const int warp = tid >> 5;
    const int gid  = lane >> 2;   // group-of-4 id = row within 8
    const int t4   = lane & 3;    // thread-in-group
    const int mrow = warp * 16;   // this warp's Q-row base within tile

    // scale = 1/sqrt(128) * log2(e): softmax done in exp2 domain
    const float SC     = 0.088388347648318447f * 1.4426950408889634f;
    const float NEGINF = __int_as_float(0xff800000);

    // ---- Load + scale + tf32-round Q tile (persistent for this CTA) ----
    const float* gQ = Q + ((size_t)head * SEQ_LEN + q0) * HEAD_DIM;
    #pragma unroll
    for (int i = tid; i < BM * HEAD_DIM / 4; i += THREADS) {
        int r = i >> 5;            // 32 float4 per 128-wide row
        int c = (i & 31) << 2;
        float4 x = *(const float4*)(gQ + r * HEAD_DIM + c);
        float* d = sQ + r * SQ_STRIDE + c;
        d[0] = __uint_as_float(f2tf(x.x * SC));
        d[1] = __uint_as_float(f2tf(x.y * SC));
        d[2] = __uint_as_float(f2tf(x.z * SC));
        d[3] = __uint_as_float(f2tf(x.w * SC));
    }

    // ---- Accumulators: O[16 x 128] per warp in mma-C layout ----
    float o[16][4];
    #pragma unroll
    for (int n = 0; n < 16; ++n) {
        o[n][0] = 0.f; o[n][1] = 0.f; o[n][2] = 0.f; o[n][3] = 0.f;
    }
    float m0 = NEGINF, m1 = NEGINF;  // row maxes (rows gid, gid+8)
    float l0 = 0.f,    l1 = 0.f;     // row sums

    const int jmax = (q0 + BM) / BN; // causal: KV tiles [0, jmax)

    for (int j = 0; j < jmax; ++j) {
        __syncthreads();   // previous iteration done with sK/sV (covers Q on j=0)

        // ---- Cooperative load of K,V tile -> SMEM (tf32-rounded) ----
        const float* gK = K + ((size_t)head * SEQ_LEN + (size_t)j * BN) * HEAD_DIM;
        const float* gV = V + ((size_t)head * SEQ_LEN + (size_t)j * BN) * HEAD_DIM;
        #pragma unroll
        for (int i = tid; i < BN * HEAD_DIM / 4; i += THREADS) {
            int r = i >> 5;
            int c = (i & 31) << 2;
            float4 kx = *(const float4*)(gK + r * HEAD_DIM + c);
            float4 vx = *(const float4*)(gV + r * HEAD_DIM + c);
            float* dk = sK + r * SK_STRIDE + c;
            dk[0] = __uint_as_float(f2tf(kx.x));
            dk[1] = __uint_as_float(f2tf(kx.y));
            dk[2] = __uint_as_float(f2tf(kx.z));
            dk[3] = __uint_as_float(f2tf(kx.w));
            float* dv = sV + r * SV_STRIDE + c;
            dv[0] = __uint_as_float(f2tf(vx.x));
            dv[1] = __uint_as_float(f2tf(vx.y));
            dv[2] = __uint_as_float(f2tf(vx.z));
            dv[3] = __uint_as_float(f2tf(vx.w));
        }
        __syncthreads();

        // Warp fully masked for this tile? (all its rows < tile's min kv)
        const bool active = (j * BN) <= (q0 + mrow + 15);
        if (active) {
            // ---- S = Q * K^T (scaled, log2 domain), 16x64 per warp ----
            float s[8][4];
            #pragma unroll
            for (int n = 0; n < 8; ++n) {
                s[n][0] = 0.f; s[n][1] = 0.f; s[n][2] = 0.f; s[n][3] = 0.f;
            }
            #pragma unroll
            for (int ks = 0; ks < 16; ++ks) {
                const float* q0p = sQ + (mrow + gid) * SQ_STRIDE + ks * 8 + t4;
                const float* q1p = q0p + 8 * SQ_STRIDE;
                unsigned a0 = __float_as_uint(q0p[0]);
                unsigned a2 = __float_as_uint(q0p[4]);
                unsigned a1 = __float_as_uint(q1p[0]);
                unsigned a3 = __float_as_uint(q1p[4]);
                #pragma unroll
                for (int nt = 0; nt < 8; ++nt) {
                    const float* kp = sK + (nt * 8 + gid) * SK_STRIDE + ks * 8 + t4;
                    unsigned b0 = __float_as_uint(kp[0]);
                    unsigned b1 = __float_as_uint(kp[4]);
                    mma_tf32(s[nt], a0, a1, a2, a3, b0, b1);
                }
            }

            // ---- Causal mask (only needed on the last two tiles) ----
            if ((j + 1) * BN > q0) {
                const int r0g = q0 + mrow + gid;
                const int r1g = r0g + 8;
                #pragma unroll
                for (int nt = 0; nt < 8; ++nt) {
                    int kb = j * BN + nt * 8 + 2 * t4;
                    if (kb     > r0g) s[nt][0] = NEGINF;
                    if (kb + 1 > r0g) s[nt][1] = NEGINF;
                    if (kb     > r1g) s[nt][2] = NEGINF;
                    if (kb + 1 > r1g) s[nt][3] = NEGINF;
                }
            }

            // ---- Online softmax (per row, exp2 domain) ----
            float mx0 = NEGINF, mx1 = NEGINF;
            #pragma unroll
            for (int nt = 0; nt < 8; ++nt) {
                mx0 = fmaxf(mx0, fmaxf(s[nt][0], s[nt][1]));
                mx1 = fmaxf(mx1, fmaxf(s[nt][2], s[nt][3]));
            }
            mx0 = fmaxf(mx0, __shfl_xor_sync(0xffffffffu, mx0, 1));
            mx0 = fmaxf(mx0, __shfl_xor_sync(0xffffffffu, mx0, 2));
            mx1 = fmaxf(mx1, __shfl_xor_sync(0xffffffffu, mx1, 1));
            mx1 = fmaxf(mx1, __shfl_xor_sync(0xffffffffu, mx1, 2));

            float mn0 = fmaxf(m0, mx0), mn1 = fmaxf(m1, mx1);
            float al0 = ex2f(m0 - mn0), al1 = ex2f(m1 - mn1);
            m0 = mn0; m1 = mn1;

            float rs0 = 0.f, rs1 = 0.f;
            float* pr0 = sP + (mrow + gid) * SP_STRIDE;
            float* pr1 = pr0 + 8 * SP_STRIDE;
            #pragma unroll
            for (int nt = 0; nt < 8; ++nt) {
                float p0 = __uint_as_float(f2tf(ex2f(s[nt][0] - mn0)));
                float p1 = __uint_as_float(f2tf(ex2f(s[nt][1] - mn0)));
                float p2 = __uint_as_float(f2tf(ex2f(s[nt][2] - mn1)));
                float p3 = __uint_as_float(f2tf(ex2f(s[nt][3] - mn1)));
                rs0 += p0 + p1;
                rs1 += p2 + p3;
                int cc = nt * 8 + 2 * t4;
                *(float2*)(pr0 + cc) = make_float2(p0, p1);
                *(float2*)(pr1 + cc) = make_float2(p2, p3);
            }
            rs0 += __shfl_xor_sync(0xffffffffu, rs0, 1);
            rs0 += __shfl_xor_sync(0xffffffffu, rs0, 2);
            rs1 += __shfl_xor_sync(0xffffffffu, rs1, 1);
            rs1 += __shfl_xor_sync(0xffffffffu, rs1, 2);
            l0 = l0 * al0 + rs0;
            l1 = l1 * al1 + rs1;

            // Rescale O
            #pragma unroll
            for (int nt = 0; nt < 16; ++nt) {
                o[nt][0] *= al0; o[nt][1] *= al0;
                o[nt][2] *= al1; o[nt][3] *= al1;
            }

            __syncwarp();  // P stores visible to whole warp

            // ---- O += P * V (P from SMEM in A-fragment layout) ----
            #pragma unroll
            for (int ks = 0; ks < 8; ++ks) {
                unsigned a0 = __float_as_uint(pr0[ks * 8 + t4]);
                unsigned a2 = __float_as_uint(pr0[ks * 8 + t4 + 4]);
                unsigned a1 = __float_as_uint(pr1[ks * 8 + t4]);
                unsigned a3 = __float_as_uint(pr1[ks * 8 + t4 + 4]);
                #pragma unroll
                for (int nt = 0; nt < 16; ++nt) {
                    const float* vp = sV + (ks * 8 + t4) * SV_STRIDE + nt * 8 + gid;
                    unsigned b0 = __float_as_uint(vp[0]);
                    unsigned b1 = __float_as_uint(vp[4 * SV_STRIDE]);
                    mma_tf32(o[nt], a0, a1, a2, a3, b0, b1);
                }
            }
        } // active
    } // KV tiles

    // ---- Epilogue: normalize and store to (S, H*DH) ----
    float inv0 = 1.0f / l0;
    float inv1 = 1.0f / l1;
    float* orow0 = Out + (size_t)(q0 + mrow + gid) * D_MODEL + head * HEAD_DIM;
    float* orow1 = orow0 + 8 * (size_t)D_MODEL;
    #pragma unroll
    for (int nt = 0; nt < 16; ++nt) {
        int cc = nt * 8 + 2 * t4;
        *(float2*)(orow0 + cc) = make_float2(o[nt][0] * inv0, o[nt][1] * inv0);
        *(float2*)(orow1 + cc) = make_float2(o[nt][2] * inv1, o[nt][3] * inv1);
    }
}

extern "C" void kernel_launch(void* const* d_in, const int* in_sizes, int n_in,
                              void* d_out, int out_size)
{
    (void)in_sizes; (void)n_in; (void)out_size;
    const float* q = (const float*)d_in[0];
    const float* k = (const float*)d_in[1];
    const float* v = (const float*)d_in[2];
    // d_in[3] = seq_length (always 4096), d_in[4] = attn_mask (causal, implicit)
    float* out = (float*)d_out;

    cudaFuncSetAttribute(fa_tf32_kernel,
                         cudaFuncAttributeMaxDynamicSharedMemorySize, SMEM_BYTES);

    dim3 grid(SEQ_LEN / BM, NUM_HEADS);
    fa_tf32_kernel<<<grid, THREADS, SMEM_BYTES>>>(q, k, v, out);
}

// round 4
// speedup vs baseline: 1.0309x; 1.0309x over previous
#include <cuda_runtime.h>
#include <cstdint>

#define H  16
#define S  4096
#define DH 128
#define DM 2048
#define BM 128
#define BN 128
#define NT 512            // 16 warps

#define SQ_STR 132
#define SK_STR 132
#define SV_STR 136

// float offsets within dynamic SMEM
#define F_Q   0
#define F_KP  (F_Q + BM*SQ_STR)     // K tile, later P tile
#define F_V   (F_KP + BM*SK_STR)
#define F_X1  (F_V + BN*SV_STR)     // rowmax exchange (128 rows x 4 warps)
#define F_X2  (F_X1 + 512)          // rowsum exchange
#define SMEM_FLOATS (F_X2 + 512)
#define SMEM_BYTES  (SMEM_FLOATS * 4)   // 208,896 B

// Prepass scratch: tf32-rounded (and Q pre-scaled) tensors
__device__ float g_Qs[H * S * DH];
__device__ float g_Ks[H * S * DH];
__device__ float g_Vs[H * S * DH];

__device__ __forceinline__ float tfr(float f){
    uint32_t r; asm("cvt.rna.tf32.f32 %0, %1;" : "=r"(r) : "f"(f));
    return __uint_as_float(r);
}
__device__ __forceinline__ float ex2f(float x){
    float r; asm("ex2.approx.ftz.f32 %0, %1;" : "=f"(r) : "f"(x)); return r;
}
__device__ __forceinline__ void mma_tf32(float c[4],
    float a0, float a1, float a2, float a3, float b0, float b1)
{
    asm volatile(
        "mma.sync.aligned.m16n8k8.row.col.f32.tf32.tf32.f32 "
        "{%0,%1,%2,%3}, {%4,%5,%6,%7}, {%8,%9}, {%0,%1,%2,%3};\n"
        : "+f"(c[0]), "+f"(c[1]), "+f"(c[2]), "+f"(c[3])
        : "r"(__float_as_uint(a0)), "r"(__float_as_uint(a1)),
          "r"(__float_as_uint(a2)), "r"(__float_as_uint(a3)),
          "r"(__float_as_uint(b0)), "r"(__float_as_uint(b1)));
}
__device__ __forceinline__ void cpa16(uint32_t dst, const float* src){
    asm volatile("cp.async.cg.shared.global [%0], [%1], 16;" :: "r"(dst), "l"(src));
}
__device__ __forceinline__ void cpa_commit(){
    asm volatile("cp.async.commit_group;" ::: "memory");
}
__device__ __forceinline__ void cpa_wait0(){
    asm volatile("cp.async.wait_group 0;" ::: "memory");
}

// ---------------- Prepass: tf32-round K,V; scale+round Q ----------------
__global__ void prep_kernel(const float* __restrict__ Q, const float* __restrict__ K,
                            const float* __restrict__ V)
{
    const float SC = 0.088388347648318447f * 1.4426950408889634f; // 1/sqrt(128)*log2e
    size_t i4 = ((size_t)blockIdx.x * blockDim.x + threadIdx.x) * 4;
    float4 q = *(const float4*)(Q + i4);
    float4 k = *(const float4*)(K + i4);
    float4 v = *(const float4*)(V + i4);
    *(float4*)(g_Qs + i4) = make_float4(tfr(q.x*SC), tfr(q.y*SC), tfr(q.z*SC), tfr(q.w*SC));
    *(float4*)(g_Ks + i4) = make_float4(tfr(k.x), tfr(k.y), tfr(k.z), tfr(k.w));
    *(float4*)(g_Vs + i4) = make_float4(tfr(v.x), tfr(v.y), tfr(v.z), tfr(v.w));
}

// ---------------- Main flash-attention kernel ----------------
extern __shared__ float sm[];

__global__ __launch_bounds__(NT, 1)
void fa_kernel(float* __restrict__ Out)
{
    const int qt   = (int)gridDim.x - 1 - (int)blockIdx.x;  // heavy tiles first
    const int head = blockIdx.y;
    const int q0   = qt * BM;
    const int tid  = threadIdx.x;
    const int lane = tid & 31;
    const int warp = tid >> 5;
    const int gid  = lane >> 2;
    const int t4   = lane & 3;
    const int rg   = warp >> 2;           // row group: rows mbase..mbase+31
    const int ch   = warp & 3;            // col quarter for S (n) and O (d)
    const int mbase = rg * 32;
    const int nbase = ch * 32;
    const int dbase = ch * 32;

    const uint32_t smb = (uint32_t)__cvta_generic_to_shared(sm);
    const float NEGINF = __int_as_float(0xff800000);

    const float* gQ  = g_Qs + ((size_t)head * S + q0) * DH;
    const float* gKh = g_Ks + (size_t)head * S * DH;
    const float* gVh = g_Vs + (size_t)head * S * DH;

    // ---- Prologue: async load Q tile + KV tile 0 ----
    // 128x128 floats per tile = 4096 float4; 32 float4 per row.
    #pragma unroll
    for (int it = 0; it < 8; ++it){
        int i = it * NT + tid;
        int row = i >> 5, c4 = (i & 31) << 2;
        cpa16(smb + (uint32_t)(F_Q + row * SQ_STR + c4) * 4, gQ + row * DH + c4);
    }
    #pragma unroll
    for (int it = 0; it < 8; ++it){
        int i = it * NT + tid;
        int row = i >> 5, c4 = (i & 31) << 2;
        cpa16(smb + (uint32_t)(F_KP + row * SK_STR + c4) * 4, gKh + row * DH + c4);
        cpa16(smb + (uint32_t)(F_V  + row * SV_STR + c4) * 4, gVh + row * DH + c4);
    }
    cpa_commit();

    float o[2][4][4];
    #pragma unroll
    for (int a = 0; a < 2; ++a)
        #pragma unroll
        for (int b = 0; b < 4; ++b)
            o[a][b][0] = o[a][b][1] = o[a][b][2] = o[a][b][3] = 0.f;
    float m[4] = {NEGINF, NEGINF, NEGINF, NEGINF};
    float l[4] = {0.f, 0.f, 0.f, 0.f};

    #pragma unroll 1
    for (int j = 0; j <= qt; ++j){
        cpa_wait0();
        __syncthreads();

        // ---- MMA1: S = Q * K^T  (32 rows x 32 cols per warp) ----
        float sa[2][4][4];
        #pragma unroll
        for (int a = 0; a < 2; ++a)
            #pragma unroll
            for (int b = 0; b < 4; ++b)
                sa[a][b][0] = sa[a][b][1] = sa[a][b][2] = sa[a][b][3] = 0.f;

        #pragma unroll
        for (int ks = 0; ks < 16; ++ks){
            int kc = ks * 8 + t4;
            const float* qr = sm + F_Q + (mbase + gid) * SQ_STR + kc;
            float a0 = qr[0],            a2 = qr[4];
            float a1 = qr[8*SQ_STR],     a3 = qr[8*SQ_STR + 4];
            float a4 = qr[16*SQ_STR],    a6 = qr[16*SQ_STR + 4];
            float a5 = qr[24*SQ_STR],    a7 = qr[24*SQ_STR + 4];
            #pragma unroll
            for (int nt = 0; nt < 4; ++nt){
                const float* kr = sm + F_KP + (nbase + nt*8 + gid) * SK_STR + kc;
                float b0 = kr[0], b1 = kr[4];
                mma_tf32(sa[0][nt], a0, a1, a2, a3, b0, b1);
                mma_tf32(sa[1][nt], a4, a5, a6, a7, b0, b1);
            }
        }

        // ---- Causal mask on diagonal tile ----
        if (j == qt){
            #pragma unroll
            for (int mg = 0; mg < 2; ++mg){
                int r0 = mbase + 16*mg + gid, r1 = r0 + 8;
                #pragma unroll
                for (int nt = 0; nt < 4; ++nt){
                    int c = nbase + nt*8 + 2*t4;
                    if (c     > r0) sa[mg][nt][0] = NEGINF;
                    if (c + 1 > r0) sa[mg][nt][1] = NEGINF;
                    if (c     > r1) sa[mg][nt][2] = NEGINF;
                    if (c + 1 > r1) sa[mg][nt][3] = NEGINF;
                }
            }
        }

        // ---- Partial row max (this warp's 32 cols), exchange across 4 warps ----
        float mx[4] = {NEGINF, NEGINF, NEGINF, NEGINF};
        #pragma unroll
        for (int nt = 0; nt < 4; ++nt){
            mx[0] = fmaxf(mx[0], fmaxf(sa[0][nt][0], sa[0][nt][1]));
            mx[1] = fmaxf(mx[1], fmaxf(sa[0][nt][2], sa[0][nt][3]));
            mx[2] = fmaxf(mx[2], fmaxf(sa[1][nt][0], sa[1][nt][1]));
            mx[3] = fmaxf(mx[3], fmaxf(sa[1][nt][2], sa[1][nt][3]));
        }
        #pragma unroll
        for (int i = 0; i < 4; ++i){
            mx[i] = fmaxf(mx[i], __shfl_xor_sync(0xffffffffu, mx[i], 1));
            mx[i] = fmaxf(mx[i], __shfl_xor_sync(0xffffffffu, mx[i], 2));
        }
        if (t4 == 0){
            #pragma unroll
            for (int i = 0; i < 4; ++i)
                sm[F_X1 + (mbase + gid + 8*i)*4 + ch] = mx[i];
        }
        __syncthreads();   // also: all warps done with K reads -> P store safe

        float mn[4], al[4];
        #pragma unroll
        for (int i = 0; i < 4; ++i){
            int b = F_X1 + (mbase + gid + 8*i)*4;
            float v = fmaxf(fmaxf(sm[b], sm[b+1]), fmaxf(sm[b+2], sm[b+3]));
            mn[i] = fmaxf(m[i], v);
            al[i] = ex2f(m[i] - mn[i]);
            m[i]  = mn[i];
        }

        // ---- P = exp2(S - m), tf32-rounded; store to K buffer; partial row sums ----
        float rs[4] = {0.f, 0.f, 0.f, 0.f};
        #pragma unroll
        for (int mg = 0; mg < 2; ++mg){
            #pragma unroll
            for (int nt = 0; nt < 4; ++nt){
                float p0 = tfr(ex2f(sa[mg][nt][0] - mn[2*mg]));
                float p1 = tfr(ex2f(sa[mg][nt][1] - mn[2*mg]));
                float p2 = tfr(ex2f(sa[mg][nt][2] - mn[2*mg+1]));
                float p3 = tfr(ex2f(sa[mg][nt][3] - mn[2*mg+1]));
                rs[2*mg]   += p0 + p1;
                rs[2*mg+1] += p2 + p3;
                int c = nbase + nt*8 + 2*t4;
                *(float2*)(sm + F_KP + (mbase + 16*mg + gid    )*SK_STR + c) = make_float2(p0, p1);
                *(float2*)(sm + F_KP + (mbase + 16*mg + gid + 8)*SK_STR + c) = make_float2(p2, p3);
            }
        }
        #pragma unroll
        for (int i = 0; i < 4; ++i){
            rs[i] += __shfl_xor_sync(0xffffffffu, rs[i], 1);
            rs[i] += __shfl_xor_sync(0xffffffffu, rs[i], 2);
        }
        if (t4 == 0){
            #pragma unroll
            for (int i = 0; i < 4; ++i)
                sm[F_X2 + (mbase + gid + 8*i)*4 + ch] = rs[i];
        }
        asm volatile("bar.sync %0, 128;" :: "r"(1 + rg) : "memory");  // group barrier

        #pragma unroll
        for (int i = 0; i < 4; ++i){
            int b = F_X2 + (mbase + gid + 8*i)*4;
            l[i] = l[i]*al[i] + (sm[b] + sm[b+1] + sm[b+2] + sm[b+3]);
        }
        // rescale O
        #pragma unroll
        for (int mg = 0; mg < 2; ++mg){
            #pragma unroll
            for (int nt = 0; nt < 4; ++nt){
                o[mg][nt][0] *= al[2*mg];   o[mg][nt][1] *= al[2*mg];
                o[mg][nt][2] *= al[2*mg+1]; o[mg][nt][3] *= al[2*mg+1];
            }
        }

        // ---- MMA2: O += P * V  (32 rows x 32 d-cols per warp) ----
        #pragma unroll
        for (int ks = 0; ks < 16; ++ks){
            int kc = ks * 8 + t4;
            const float* pr = sm + F_KP + (mbase + gid) * SK_STR + kc;
            float a0 = pr[0],            a2 = pr[4];
            float a1 = pr[8*SK_STR],     a3 = pr[8*SK_STR + 4];
            float a4 = pr[16*SK_STR],    a6 = pr[16*SK_STR + 4];
            float a5 = pr[24*SK_STR],    a7 = pr[24*SK_STR + 4];
            #pragma unroll
            for (int nt = 0; nt < 4; ++nt){
                const float* vr = sm + F_V + kc * SV_STR + dbase + nt*8 + gid;
                float b0 = vr[0], b1 = vr[4*SV_STR];
                mma_tf32(o[0][nt], a0, a1, a2, a3, b0, b1);
                mma_tf32(o[1][nt], a4, a5, a6, a7, b0, b1);
            }
        }

        __syncthreads();   // all reads of P (K buf) and V done
        if (j < qt){
            const float* gK = gKh + (size_t)(j + 1) * BN * DH;
            const float* gV = gVh + (size_t)(j + 1) * BN * DH;
            #pragma unroll
            for (int it = 0; it < 8; ++it){
                int i = it * NT + tid;
                int row = i >> 5, c4 = (i & 31) << 2;
                cpa16(smb + (uint32_t)(F_KP + row * SK_STR + c4) * 4, gK + row * DH + c4);
                cpa16(smb + (uint32_t)(F_V  + row * SV_STR + c4) * 4, gV + row * DH + c4);
            }
            cpa_commit();
        }
    }

    // ---- Epilogue: O / l -> Out[(q0+row), head*128 + d] ----
    #pragma unroll
    for (int mg = 0; mg < 2; ++mg){
        int r0 = q0 + mbase + 16*mg + gid;
        float i0 = 1.0f / l[2*mg];
        float i1 = 1.0f / l[2*mg + 1];
        #pragma unroll
        for (int nt = 0; nt < 4; ++nt){
            int c = head * DH + dbase + nt*8 + 2*t4;
            *(float2*)(Out + (size_t)r0 * DM + c) =
                make_float2(o[mg][nt][0] * i0, o[mg][nt][1] * i0);
            *(float2*)(Out + (size_t)(r0 + 8) * DM + c) =
                make_float2(o[mg][nt][2] * i1, o[mg][nt][3] * i1);
        }
    }
}

extern "C" void kernel_launch(void* const* d_in, const int* in_sizes, int n_in,
                              void* d_out, int out_size)
{
    (void)in_sizes; (void)n_in; (void)out_size;
    const float* q = (const float*)d_in[0];
    const float* k = (const float*)d_in[1];
    const float* v = (const float*)d_in[2];
    float* out = (float*)d_out;

    // Prepass: tf32-round all operands (Q pre-scaled) into device scratch
    prep_kernel<<<(H * S * DH) / 4 / 256, 256>>>(q, k, v);

    cudaFuncSetAttribute(fa_kernel,
                         cudaFuncAttributeMaxDynamicSharedMemorySize, SMEM_BYTES);
    dim3 grid(S / BM, H);
    fa_kernel<<<grid, NT, SMEM_BYTES>>>(out);
}